// round 16
// baseline (speedup 1.0000x reference)
#include <cuda_runtime.h>
#include <cuda_fp16.h>
#include <cstdint>

// ---------------- problem constants ----------------
#define B_SZ   4096
#define T_SZ   4
#define C_SZ   1024
#define H_SZ   8
#define DH_SZ  128
#define N_QKV  3072
#define SCALE_F 0.08838834764831845f   // 128^-0.5
#define LN_EPS 1e-5f

// ---------------- device scratch (no runtime alloc allowed) ----------------
__device__ __half g_Wqkv_h [(size_t)T_SZ * N_QKV * C_SZ];   // [t][n][k] fp16
__device__ __half g_Wproj_h[(size_t)T_SZ * C_SZ  * C_SZ];   // [t][n][k] fp16
__device__ __half g_featsh [(size_t)B_SZ * T_SZ * C_SZ];    // feats fp16
__device__ __half g_qkv    [(size_t)B_SZ * T_SZ * N_QKV];   // qkv fp16; later reused as x fp16
__device__ __half g_ctx    [(size_t)B_SZ * T_SZ * C_SZ];    // [b][t][C] fp16

// ---------------- helpers ----------------
__device__ __forceinline__ uint32_t smem_u32(const void* p) {
    uint32_t a;
    asm("{ .reg .u64 t; cvta.to.shared.u64 t, %1; cvt.u32.u64 %0, t; }" : "=r"(a) : "l"(p));
    return a;
}
__device__ __forceinline__ void mma16(float* c, const uint32_t* a, uint32_t b0, uint32_t b1) {
    asm volatile(
        "mma.sync.aligned.m16n8k16.row.col.f32.f16.f16.f32 "
        "{%0,%1,%2,%3}, {%4,%5,%6,%7}, {%8,%9}, {%0,%1,%2,%3};"
        : "+f"(c[0]), "+f"(c[1]), "+f"(c[2]), "+f"(c[3])
        : "r"(a[0]), "r"(a[1]), "r"(a[2]), "r"(a[3]), "r"(b0), "r"(b1));
}
__device__ __forceinline__ void ldsm4(uint32_t* r, uint32_t addr) {
    asm volatile("ldmatrix.sync.aligned.m8n8.x4.shared.b16 {%0,%1,%2,%3}, [%4];"
                 : "=r"(r[0]), "=r"(r[1]), "=r"(r[2]), "=r"(r[3]) : "r"(addr));
}
#define CP_ASYNC16(dst, src)  asm volatile("cp.async.cg.shared.global [%0], [%1], 16;" :: "r"(dst), "l"(src))
#define CP_COMMIT()           asm volatile("cp.async.commit_group;" ::: "memory")
#define CP_WAIT1()            asm volatile("cp.async.wait_group 1;" ::: "memory")

// ---------------- GEMM: D[m,n] = sum_k A[m,k] * Wt[t][n][k] (+bias, +resid) ----------------
// A row m lives at A[(m*T + t)*C + k] (fp16). fp32 accumulate.
// 128x128 tile, 8 warps (2x4), warp tile 64x32, 3-stage cp.async, 2 CTAs/SM.
static constexpr int MT = 128;
static constexpr int NT = 128;
static constexpr int KT = 64;                         // K halves per stage (128 B/row)
static constexpr int NSTG = 3;
static constexpr int NTHR = 256;
static constexpr int LDH = 72;                        // padded half-stride per row (144 B)
static constexpr int A_HALVES = MT * LDH;             // 9216
static constexpr int STG_HALVES = (MT + NT) * LDH;    // 18432
static constexpr int GEMM_SMEM = NSTG * STG_HALVES * 2;   // 110592 B -> 2 CTAs/SM

// OUT_HALF: store __half; RESID: add fp16 residual (works with either output type).
template <int NTOT, bool RESID, bool OUT_HALF>
__global__ __launch_bounds__(NTHR, 2)
void gemm_kernel(const __half* __restrict__ A,
                 const __half* __restrict__ Wt,
                 const float* __restrict__ bias,
                 const __half* __restrict__ resid,
                 void* __restrict__ out_v) {
    extern __shared__ __half sm[];
    const int tid = threadIdx.x;
    const int wid = tid >> 5, lane = tid & 31;
    const int warp_m = wid >> 2;        // 0..1  (64 rows each)
    const int warp_n = wid & 3;         // 0..3  (32 cols each)
    const int g = lane >> 2, q = lane & 3;
    const int n0 = blockIdx.x * NT;
    const int m0 = blockIdx.y * MT;
    const int t  = blockIdx.z;

    // ldmatrix x4 source-row assignment (grp = lane>>3, lr = lane&7):
    // A: m0=(rows g0-7, k0-7) m1=(g8-15, k0-7) m2=(g0-7, k8-15) m3=(g8-15, k8-15)
    // B: m0=(n0-7, k0-7) m1=(n0-7, k8-15) m2=(n8-15, k0-7) m3=(n8-15, k8-15)
    const int grp = lane >> 3, lr = lane & 7;
    const uint32_t sm_base = smem_u32(sm);
    const uint32_t a_off = (uint32_t)(((warp_m * 64 + (grp & 1) * 8 + lr) * LDH + (grp >> 1) * 8) * 2);
    const uint32_t b_off = (uint32_t)(((warp_n * 32 + (grp >> 1) * 8 + lr) * LDH + (grp & 1) * 8) * 2);

    auto load_stage = [&](int ck, int slot) {
        const int k0 = ck * KT;
        __half* As = sm + slot * STG_HALVES;
        __half* Bs = As + A_HALVES;
        #pragma unroll
        for (int p = 0; p < 4; p++) {              // A: 128 rows x 8 x 16B
            int idx = tid + p * NTHR;
            int r = idx >> 3, j = idx & 7;
            const __half* src = A + ((size_t)(m0 + r) * T_SZ + t) * C_SZ + k0 + j * 8;
            CP_ASYNC16(smem_u32(As + r * LDH + j * 8), src);
        }
        #pragma unroll
        for (int p = 0; p < 4; p++) {              // B: 128 rows x 8 x 16B
            int idx = tid + p * NTHR;
            int r = idx >> 3, j = idx & 7;
            const __half* src = Wt + ((size_t)t * NTOT + n0 + r) * C_SZ + k0 + j * 8;
            CP_ASYNC16(smem_u32(Bs + r * LDH + j * 8), src);
        }
    };

    float acc[4][4][4];
    #pragma unroll
    for (int mi = 0; mi < 4; mi++)
        #pragma unroll
        for (int ni = 0; ni < 4; ni++)
            #pragma unroll
            for (int c = 0; c < 4; c++) acc[mi][ni][c] = 0.f;

    load_stage(0, 0); CP_COMMIT();
    load_stage(1, 1); CP_COMMIT();

    const int NKC = C_SZ / KT;          // 16
    for (int i = 0; i < NKC; i++) {
        CP_WAIT1();
        __syncthreads();
        const uint32_t As_u = sm_base + (uint32_t)((i % NSTG) * STG_HALVES) * 2u;
        const uint32_t Bs_u = As_u + (uint32_t)A_HALVES * 2u;
        #pragma unroll
        for (int ks = 0; ks < 4; ks++) {            // 4 x k16 per stage
            const uint32_t kb = (uint32_t)(ks * 16 * 2);
            uint32_t a[4][4];
            #pragma unroll
            for (int mi = 0; mi < 4; mi++)
                ldsm4(a[mi], As_u + a_off + (uint32_t)(mi * 16 * LDH * 2) + kb);
            uint32_t b[2][4];
            #pragma unroll
            for (int p = 0; p < 2; p++)
                ldsm4(b[p], Bs_u + b_off + (uint32_t)(p * 16 * LDH * 2) + kb);
            #pragma unroll
            for (int ni = 0; ni < 4; ni++) {
                const uint32_t b0 = b[ni >> 1][(ni & 1) * 2];       // k0-7 of this n-octet
                const uint32_t b1 = b[ni >> 1][(ni & 1) * 2 + 1];   // k8-15 of this n-octet
                #pragma unroll
                for (int mi = 0; mi < 4; mi++) mma16(acc[mi][ni], a[mi], b0, b1);
            }
        }
        if (i + 2 < NKC) load_stage(i + 2, (i + 2) % NSTG);
        CP_COMMIT();
    }

    // epilogue: register -> gmem, fused bias (+fp16 residual); fp16 or fp32 output
    #pragma unroll
    for (int mi = 0; mi < 4; mi++) {
        #pragma unroll
        for (int ni = 0; ni < 4; ni++) {
            const int row = m0 + warp_m * 64 + mi * 16 + g;
            const int col = n0 + warp_n * 32 + ni * 8 + q * 2;
            const float2 bb = *reinterpret_cast<const float2*>(bias + (size_t)t * NTOT + col);
            float2 v0 = make_float2(acc[mi][ni][0] + bb.x, acc[mi][ni][1] + bb.y);
            float2 v1 = make_float2(acc[mi][ni][2] + bb.x, acc[mi][ni][3] + bb.y);
            if (RESID) {
                const float2 r0 = __half22float2(*reinterpret_cast<const __half2*>(
                    resid + ((size_t)row * T_SZ + t) * C_SZ + col));
                const float2 r1 = __half22float2(*reinterpret_cast<const __half2*>(
                    resid + ((size_t)(row + 8) * T_SZ + t) * C_SZ + col));
                v0.x += r0.x; v0.y += r0.y; v1.x += r1.x; v1.y += r1.y;
            }
            if (OUT_HALF) {
                __half* out = (__half*)out_v;
                *reinterpret_cast<__half2*>(out + ((size_t)row * T_SZ + t) * NTOT + col) =
                    __floats2half2_rn(v0.x, v0.y);
                *reinterpret_cast<__half2*>(out + ((size_t)(row + 8) * T_SZ + t) * NTOT + col) =
                    __floats2half2_rn(v1.x, v1.y);
            } else {
                float* out = (float*)out_v;
                *reinterpret_cast<float2*>(out + ((size_t)row * T_SZ + t) * NTOT + col) = v0;
                *reinterpret_cast<float2*>(out + ((size_t)(row + 8) * T_SZ + t) * NTOT + col) = v1;
            }
        }
    }
}

// ---------------- weight transpose + fp16 convert: W[t][k][n] -> Wt[t][n][k] ----------------
// 64x64 tiles: float4 gmem reads (256B rows), half2 writes (128B contiguous rows).
__global__ __launch_bounds__(256) void transpose_kernel(const float* __restrict__ in,
                                                        __half* __restrict__ out,
                                                        int R, int Ncols) {
    __shared__ float tile[64][65];     // tile[n][r]
    const int t = blockIdx.z;
    const float* inp = in + (size_t)t * R * Ncols;
    __half* outp = out + (size_t)t * R * Ncols;
    const int n0 = blockIdx.x * 64, r0 = blockIdx.y * 64;
    #pragma unroll
    for (int p = 0; p < 4; p++) {
        int id = threadIdx.x + p * 256;     // 0..1023
        int r  = id >> 4;                   // 0..63
        int c4 = (id & 15) * 4;
        float4 v = *reinterpret_cast<const float4*>(inp + (size_t)(r0 + r) * Ncols + n0 + c4);
        tile[c4 + 0][r] = v.x;
        tile[c4 + 1][r] = v.y;
        tile[c4 + 2][r] = v.z;
        tile[c4 + 3][r] = v.w;
    }
    __syncthreads();
    #pragma unroll
    for (int p = 0; p < 8; p++) {
        int id = threadIdx.x + p * 256;     // 0..2047
        int n  = id >> 5;                   // 0..63
        int r2 = (id & 31) * 2;
        __half2 h = __floats2half2_rn(tile[n][r2], tile[n][r2 + 1]);
        *reinterpret_cast<__half2*>(outp + (size_t)(n0 + n) * R + r0 + r2) = h;
    }
}

// ---------------- fp16 convert-copy (feats -> g_featsh) ----------------
__global__ __launch_bounds__(256) void convert_kernel(const float4* __restrict__ in,
                                                      __half2* __restrict__ out) {
    const int idx = blockIdx.x * 256 + threadIdx.x;
    float4 v = in[idx];
    out[idx * 2 + 0] = __floats2half2_rn(v.x, v.y);
    out[idx * 2 + 1] = __floats2half2_rn(v.z, v.w);
}

// ---------------- cross-task attention (T=4; one block per b, warp = head) ----------------
// qkv is fp16; all math fp32 in registers; emits ctx fp16.
__global__ __launch_bounds__(256) void attn_kernel(const __half* __restrict__ qkv,
                                                   __half* __restrict__ ctx) {
    const int b = blockIdx.x;
    const int h = threadIdx.x >> 5;     // 8 warps = 8 heads
    const int l = threadIdx.x & 31;
    const size_t base = (size_t)b * T_SZ * N_QKV + h * DH_SZ + l * 4;

    float4 q[4], k[4], v[4];
    #pragma unroll
    for (int tt = 0; tt < 4; tt++) {
        const __half2* qp = reinterpret_cast<const __half2*>(qkv + base + (size_t)tt * N_QKV);
        const __half2* kp = reinterpret_cast<const __half2*>(qkv + base + (size_t)tt * N_QKV + C_SZ);
        const __half2* vp = reinterpret_cast<const __half2*>(qkv + base + (size_t)tt * N_QKV + 2 * C_SZ);
        float2 f0 = __half22float2(qp[0]), f1 = __half22float2(qp[1]);
        q[tt] = make_float4(f0.x, f0.y, f1.x, f1.y);
        f0 = __half22float2(kp[0]); f1 = __half22float2(kp[1]);
        k[tt] = make_float4(f0.x, f0.y, f1.x, f1.y);
        f0 = __half22float2(vp[0]); f1 = __half22float2(vp[1]);
        v[tt] = make_float4(f0.x, f0.y, f1.x, f1.y);
    }
    float s[16];
    #pragma unroll
    for (int qt = 0; qt < 4; qt++)
        #pragma unroll
        for (int kt = 0; kt < 4; kt++)
            s[qt * 4 + kt] = q[qt].x * k[kt].x + q[qt].y * k[kt].y +
                             q[qt].z * k[kt].z + q[qt].w * k[kt].w;
    #pragma unroll
    for (int off = 16; off; off >>= 1)
        #pragma unroll
        for (int i = 0; i < 16; i++)
            s[i] += __shfl_xor_sync(0xffffffffu, s[i], off);

    #pragma unroll
    for (int qt = 0; qt < 4; qt++) {
        float sc[4];
        #pragma unroll
        for (int kt = 0; kt < 4; kt++) sc[kt] = s[qt * 4 + kt] * SCALE_F;
        float mx = fmaxf(fmaxf(sc[0], sc[1]), fmaxf(sc[2], sc[3]));
        float e[4], sum = 0.f;
        #pragma unroll
        for (int kt = 0; kt < 4; kt++) { e[kt] = __expf(sc[kt] - mx); sum += e[kt]; }
        const float inv = 1.f / sum;
        float4 acc = make_float4(0.f, 0.f, 0.f, 0.f);
        #pragma unroll
        for (int kt = 0; kt < 4; kt++) {
            const float a = e[kt] * inv;
            acc.x += a * v[kt].x; acc.y += a * v[kt].y;
            acc.z += a * v[kt].z; acc.w += a * v[kt].w;
        }
        __half2* dst = reinterpret_cast<__half2*>(
            ctx + ((size_t)b * T_SZ + qt) * C_SZ + h * DH_SZ + l * 4);
        dst[0] = __floats2half2_rn(acc.x, acc.y);
        dst[1] = __floats2half2_rn(acc.z, acc.w);
    }
}

// ---------------- LayerNorm: fp16 x -> fp32 out, per (b,t) row of C=1024 ----------------
__global__ __launch_bounds__(256) void ln_kernel(const __half* __restrict__ x,
                                                 const float* __restrict__ gamma,
                                                 const float* __restrict__ beta,
                                                 float* __restrict__ out) {
    __shared__ float rs[8], rq[8];
    const size_t row = blockIdx.x;
    const __half2* xr = reinterpret_cast<const __half2*>(x + row * C_SZ);
    const int tid = threadIdx.x;
    const float2 a0 = __half22float2(xr[tid * 2]);
    const float2 a1 = __half22float2(xr[tid * 2 + 1]);
    float4 v = make_float4(a0.x, a0.y, a1.x, a1.y);
    float s = v.x + v.y + v.z + v.w;
    float qq = v.x * v.x + v.y * v.y + v.z * v.z + v.w * v.w;
    #pragma unroll
    for (int o = 16; o; o >>= 1) {
        s  += __shfl_xor_sync(0xffffffffu, s,  o);
        qq += __shfl_xor_sync(0xffffffffu, qq, o);
    }
    if ((tid & 31) == 0) { rs[tid >> 5] = s; rq[tid >> 5] = qq; }
    __syncthreads();
    float S = 0.f, Q = 0.f;
    #pragma unroll
    for (int i = 0; i < 8; i++) { S += rs[i]; Q += rq[i]; }
    const float mu  = S * (1.f / C_SZ);
    const float var = Q * (1.f / C_SZ) - mu * mu;
    const float inv = rsqrtf(var + LN_EPS);
    const float4 g = reinterpret_cast<const float4*>(gamma)[tid];
    const float4 b = reinterpret_cast<const float4*>(beta)[tid];
    float4 o;
    o.x = (v.x - mu) * inv * g.x + b.x;
    o.y = (v.y - mu) * inv * g.y + b.y;
    o.z = (v.z - mu) * inv * g.z + b.z;
    o.w = (v.w - mu) * inv * g.w + b.w;
    reinterpret_cast<float4*>(out + row * C_SZ)[tid] = o;
}

// ---------------- launcher ----------------
extern "C" void kernel_launch(void* const* d_in, const int* in_sizes, int n_in,
                              void* d_out, int out_size) {
    (void)in_sizes; (void)n_in; (void)out_size;
    const float* feats = (const float*)d_in[0];
    const float* Wqkv  = (const float*)d_in[1];
    const float* bqkv  = (const float*)d_in[2];
    const float* Wproj = (const float*)d_in[3];
    const float* bproj = (const float*)d_in[4];
    const float* gamma = (const float*)d_in[5];
    const float* beta  = (const float*)d_in[6];
    float* out = (float*)d_out;

    __half *wqkv_h, *wproj_h, *featsh, *qkv, *ctx;
    cudaGetSymbolAddress((void**)&wqkv_h, g_Wqkv_h);
    cudaGetSymbolAddress((void**)&wproj_h, g_Wproj_h);
    cudaGetSymbolAddress((void**)&featsh, g_featsh);
    cudaGetSymbolAddress((void**)&qkv, g_qkv);
    cudaGetSymbolAddress((void**)&ctx, g_ctx);
    __half* xh = qkv;   // reuse qkv scratch for post-GEMM2 x (attn consumed qkv already)

    cudaFuncSetAttribute(gemm_kernel<N_QKV, false, true>,
                         cudaFuncAttributeMaxDynamicSharedMemorySize, GEMM_SMEM);
    cudaFuncSetAttribute(gemm_kernel<C_SZ, true, true>,
                         cudaFuncAttributeMaxDynamicSharedMemorySize, GEMM_SMEM);

    // 1. convert operands to fp16: weights (64x64 transpose+convert), feats (convert-copy)
    transpose_kernel<<<dim3(N_QKV / 64, C_SZ / 64, T_SZ), 256>>>(Wqkv, wqkv_h, C_SZ, N_QKV);
    transpose_kernel<<<dim3(C_SZ / 64, C_SZ / 64, T_SZ), 256>>>(Wproj, wproj_h, C_SZ, C_SZ);
    convert_kernel<<<(B_SZ * T_SZ * C_SZ / 4) / 256, 256>>>(
        (const float4*)feats, (__half2*)featsh);
    // 2. QKV projection -> fp16 qkv (fp16 mma.sync m16n8k16 + ldmatrix, 2 CTAs/SM)
    gemm_kernel<N_QKV, false, true><<<dim3(N_QKV / NT, B_SZ / MT, T_SZ), NTHR, GEMM_SMEM>>>(
        featsh, wqkv_h, bqkv, nullptr, qkv);
    // 3. cross-task attention (fp16 in, fp16 out)
    attn_kernel<<<B_SZ, 256>>>(qkv, ctx);
    // 4. output projection + bias + fp16 residual(featsh) -> fp16 x (reused qkv scratch)
    gemm_kernel<C_SZ, true, true><<<dim3(C_SZ / NT, B_SZ / MT, T_SZ), NTHR, GEMM_SMEM>>>(
        ctx, wproj_h, bproj, featsh, xh);
    // 5. LayerNorm: fp16 x -> fp32 d_out
    ln_kernel<<<B_SZ * T_SZ, 256>>>(xh, gamma, beta, out);
}

// round 17
// speedup vs baseline: 1.0294x; 1.0294x over previous
#include <cuda_runtime.h>
#include <cuda_fp16.h>
#include <cstdint>

// ---------------- problem constants ----------------
#define B_SZ   4096
#define T_SZ   4
#define C_SZ   1024
#define H_SZ   8
#define DH_SZ  128
#define N_QKV  3072
#define SCALE_F 0.08838834764831845f   // 128^-0.5
#define LN_EPS 1e-5f

// ---------------- device scratch (no runtime alloc allowed) ----------------
__device__ __half g_Wqkv_h [(size_t)T_SZ * N_QKV * C_SZ];   // [t][n][k] fp16
__device__ __half g_Wproj_h[(size_t)T_SZ * C_SZ  * C_SZ];   // [t][n][k] fp16
__device__ __half g_featsh [(size_t)B_SZ * T_SZ * C_SZ];    // feats fp16
__device__ __half g_qkv    [(size_t)B_SZ * T_SZ * N_QKV];   // qkv fp16; later reused as x fp16
__device__ __half g_ctx    [(size_t)B_SZ * T_SZ * C_SZ];    // [b][t][C] fp16

// ---------------- helpers ----------------
__device__ __forceinline__ uint32_t smem_u32(const void* p) {
    uint32_t a;
    asm("{ .reg .u64 t; cvta.to.shared.u64 t, %1; cvt.u32.u64 %0, t; }" : "=r"(a) : "l"(p));
    return a;
}
__device__ __forceinline__ void mma16(float* c, const uint32_t* a, uint32_t b0, uint32_t b1) {
    asm volatile(
        "mma.sync.aligned.m16n8k16.row.col.f32.f16.f16.f32 "
        "{%0,%1,%2,%3}, {%4,%5,%6,%7}, {%8,%9}, {%0,%1,%2,%3};"
        : "+f"(c[0]), "+f"(c[1]), "+f"(c[2]), "+f"(c[3])
        : "r"(a[0]), "r"(a[1]), "r"(a[2]), "r"(a[3]), "r"(b0), "r"(b1));
}
__device__ __forceinline__ void ldsm4(uint32_t* r, uint32_t addr) {
    asm volatile("ldmatrix.sync.aligned.m8n8.x4.shared.b16 {%0,%1,%2,%3}, [%4];"
                 : "=r"(r[0]), "=r"(r[1]), "=r"(r[2]), "=r"(r[3]) : "r"(addr));
}
#define CP_ASYNC16(dst, src)  asm volatile("cp.async.cg.shared.global [%0], [%1], 16;" :: "r"(dst), "l"(src))
#define CP_COMMIT()           asm volatile("cp.async.commit_group;" ::: "memory")
#define CP_WAIT1()            asm volatile("cp.async.wait_group 1;" ::: "memory")

// ---------------- GEMM: D[m,n] = sum_k A[m,k] * Wt[t][n][k] (+bias, +resid) ----------------
// A row m lives at A[(m*T + t)*C + k] (fp16). fp32 accumulate.
// 128x128 tile, 8 warps (2x4), warp tile 64x32, 3-stage cp.async, 2 CTAs/SM.
// Stage loads are SPREAD across the 4 ks-groups (2 cp.async/thread after each group).
static constexpr int MT = 128;
static constexpr int NT = 128;
static constexpr int KT = 64;                         // K halves per stage (128 B/row)
static constexpr int NSTG = 3;
static constexpr int NTHR = 256;
static constexpr int LDH = 72;                        // padded half-stride per row (144 B)
static constexpr int A_HALVES = MT * LDH;             // 9216
static constexpr int STG_HALVES = (MT + NT) * LDH;    // 18432
static constexpr int GEMM_SMEM = NSTG * STG_HALVES * 2;   // 110592 B -> 2 CTAs/SM

// OUT_HALF: store __half; RESID: add fp16 residual (works with either output type).
template <int NTOT, bool RESID, bool OUT_HALF>
__global__ __launch_bounds__(NTHR, 2)
void gemm_kernel(const __half* __restrict__ A,
                 const __half* __restrict__ Wt,
                 const float* __restrict__ bias,
                 const __half* __restrict__ resid,
                 void* __restrict__ out_v) {
    extern __shared__ __half sm[];
    const int tid = threadIdx.x;
    const int wid = tid >> 5, lane = tid & 31;
    const int warp_m = wid >> 2;        // 0..1  (64 rows each)
    const int warp_n = wid & 3;         // 0..3  (32 cols each)
    const int g = lane >> 2, q = lane & 3;
    const int n0 = blockIdx.x * NT;
    const int m0 = blockIdx.y * MT;
    const int t  = blockIdx.z;

    // ldmatrix x4 source-row assignment (grp = lane>>3, lr = lane&7):
    // A: m0=(rows g0-7, k0-7) m1=(g8-15, k0-7) m2=(g0-7, k8-15) m3=(g8-15, k8-15)
    // B: m0=(n0-7, k0-7) m1=(n0-7, k8-15) m2=(n8-15, k0-7) m3=(n8-15, k8-15)
    const int grp = lane >> 3, lr = lane & 7;
    const uint32_t sm_base = smem_u32(sm);
    const uint32_t a_off = (uint32_t)(((warp_m * 64 + (grp & 1) * 8 + lr) * LDH + (grp >> 1) * 8) * 2);
    const uint32_t b_off = (uint32_t)(((warp_n * 32 + (grp >> 1) * 8 + lr) * LDH + (grp & 1) * 8) * 2);

    // one part = 1 A-row-chunk + 1 B-row-chunk (2 cp.async per thread)
    auto load_part = [&](int ck, int slot, int p) {
        const int k0 = ck * KT;
        __half* As = sm + slot * STG_HALVES;
        __half* Bs = As + A_HALVES;
        {
            int idx = tid + p * NTHR;              // A: 128 rows x 8 x 16B
            int r = idx >> 3, j = idx & 7;
            const __half* src = A + ((size_t)(m0 + r) * T_SZ + t) * C_SZ + k0 + j * 8;
            CP_ASYNC16(smem_u32(As + r * LDH + j * 8), src);
        }
        {
            int idx = tid + p * NTHR;              // B: 128 rows x 8 x 16B
            int r = idx >> 3, j = idx & 7;
            const __half* src = Wt + ((size_t)t * NTOT + n0 + r) * C_SZ + k0 + j * 8;
            CP_ASYNC16(smem_u32(Bs + r * LDH + j * 8), src);
        }
    };
    auto load_stage = [&](int ck, int slot) {
        #pragma unroll
        for (int p = 0; p < 4; p++) load_part(ck, slot, p);
    };

    float acc[4][4][4];
    #pragma unroll
    for (int mi = 0; mi < 4; mi++)
        #pragma unroll
        for (int ni = 0; ni < 4; ni++)
            #pragma unroll
            for (int c = 0; c < 4; c++) acc[mi][ni][c] = 0.f;

    load_stage(0, 0); CP_COMMIT();
    load_stage(1, 1); CP_COMMIT();

    const int NKC = C_SZ / KT;          // 16
    for (int i = 0; i < NKC; i++) {
        CP_WAIT1();
        __syncthreads();
        const uint32_t As_u = sm_base + (uint32_t)((i % NSTG) * STG_HALVES) * 2u;
        const uint32_t Bs_u = As_u + (uint32_t)A_HALVES * 2u;
        const bool pf = (i + 2 < NKC);
        const int pf_slot = (i + 2) % NSTG;
        #pragma unroll
        for (int ks = 0; ks < 4; ks++) {            // 4 x k16 per stage
            const uint32_t kb = (uint32_t)(ks * 16 * 2);
            uint32_t a[4][4];
            #pragma unroll
            for (int mi = 0; mi < 4; mi++)
                ldsm4(a[mi], As_u + a_off + (uint32_t)(mi * 16 * LDH * 2) + kb);
            uint32_t b[2][4];
            #pragma unroll
            for (int p = 0; p < 2; p++)
                ldsm4(b[p], Bs_u + b_off + (uint32_t)(p * 16 * LDH * 2) + kb);
            #pragma unroll
            for (int ni = 0; ni < 4; ni++) {
                const uint32_t b0 = b[ni >> 1][(ni & 1) * 2];       // k0-7 of this n-octet
                const uint32_t b1 = b[ni >> 1][(ni & 1) * 2 + 1];   // k8-15 of this n-octet
                #pragma unroll
                for (int mi = 0; mi < 4; mi++) mma16(acc[mi][ni], a[mi], b0, b1);
            }
            if (pf) load_part(i + 2, pf_slot, ks);  // spread: 2 cp.async after each ks group
        }
        CP_COMMIT();
    }

    // epilogue: register -> gmem, fused bias (+fp16 residual); fp16 or fp32 output
    #pragma unroll
    for (int mi = 0; mi < 4; mi++) {
        #pragma unroll
        for (int ni = 0; ni < 4; ni++) {
            const int row = m0 + warp_m * 64 + mi * 16 + g;
            const int col = n0 + warp_n * 32 + ni * 8 + q * 2;
            const float2 bb = *reinterpret_cast<const float2*>(bias + (size_t)t * NTOT + col);
            float2 v0 = make_float2(acc[mi][ni][0] + bb.x, acc[mi][ni][1] + bb.y);
            float2 v1 = make_float2(acc[mi][ni][2] + bb.x, acc[mi][ni][3] + bb.y);
            if (RESID) {
                const float2 r0 = __half22float2(*reinterpret_cast<const __half2*>(
                    resid + ((size_t)row * T_SZ + t) * C_SZ + col));
                const float2 r1 = __half22float2(*reinterpret_cast<const __half2*>(
                    resid + ((size_t)(row + 8) * T_SZ + t) * C_SZ + col));
                v0.x += r0.x; v0.y += r0.y; v1.x += r1.x; v1.y += r1.y;
            }
            if (OUT_HALF) {
                __half* out = (__half*)out_v;
                *reinterpret_cast<__half2*>(out + ((size_t)row * T_SZ + t) * NTOT + col) =
                    __floats2half2_rn(v0.x, v0.y);
                *reinterpret_cast<__half2*>(out + ((size_t)(row + 8) * T_SZ + t) * NTOT + col) =
                    __floats2half2_rn(v1.x, v1.y);
            } else {
                float* out = (float*)out_v;
                *reinterpret_cast<float2*>(out + ((size_t)row * T_SZ + t) * NTOT + col) = v0;
                *reinterpret_cast<float2*>(out + ((size_t)(row + 8) * T_SZ + t) * NTOT + col) = v1;
            }
        }
    }
}

// ---------------- weight transpose + fp16 convert: W[t][k][n] -> Wt[t][n][k] ----------------
// 64x64 tiles: float4 gmem reads (256B rows), half2 writes (128B contiguous rows).
__global__ __launch_bounds__(256) void transpose_kernel(const float* __restrict__ in,
                                                        __half* __restrict__ out,
                                                        int R, int Ncols) {
    __shared__ float tile[64][65];     // tile[n][r]
    const int t = blockIdx.z;
    const float* inp = in + (size_t)t * R * Ncols;
    __half* outp = out + (size_t)t * R * Ncols;
    const int n0 = blockIdx.x * 64, r0 = blockIdx.y * 64;
    #pragma unroll
    for (int p = 0; p < 4; p++) {
        int id = threadIdx.x + p * 256;     // 0..1023
        int r  = id >> 4;                   // 0..63
        int c4 = (id & 15) * 4;
        float4 v = *reinterpret_cast<const float4*>(inp + (size_t)(r0 + r) * Ncols + n0 + c4);
        tile[c4 + 0][r] = v.x;
        tile[c4 + 1][r] = v.y;
        tile[c4 + 2][r] = v.z;
        tile[c4 + 3][r] = v.w;
    }
    __syncthreads();
    #pragma unroll
    for (int p = 0; p < 8; p++) {
        int id = threadIdx.x + p * 256;     // 0..2047
        int n  = id >> 5;                   // 0..63
        int r2 = (id & 31) * 2;
        __half2 h = __floats2half2_rn(tile[n][r2], tile[n][r2 + 1]);
        *reinterpret_cast<__half2*>(outp + (size_t)(n0 + n) * R + r0 + r2) = h;
    }
}

// ---------------- fp16 convert-copy (feats -> g_featsh) ----------------
__global__ __launch_bounds__(256) void convert_kernel(const float4* __restrict__ in,
                                                      __half2* __restrict__ out) {
    const int idx = blockIdx.x * 256 + threadIdx.x;
    float4 v = in[idx];
    out[idx * 2 + 0] = __floats2half2_rn(v.x, v.y);
    out[idx * 2 + 1] = __floats2half2_rn(v.z, v.w);
}

// ---------------- cross-task attention (T=4; one block per b, warp = head) ----------------
// qkv is fp16; all math fp32 in registers; emits ctx fp16.
__global__ __launch_bounds__(256) void attn_kernel(const __half* __restrict__ qkv,
                                                   __half* __restrict__ ctx) {
    const int b = blockIdx.x;
    const int h = threadIdx.x >> 5;     // 8 warps = 8 heads
    const int l = threadIdx.x & 31;
    const size_t base = (size_t)b * T_SZ * N_QKV + h * DH_SZ + l * 4;

    float4 q[4], k[4], v[4];
    #pragma unroll
    for (int tt = 0; tt < 4; tt++) {
        const __half2* qp = reinterpret_cast<const __half2*>(qkv + base + (size_t)tt * N_QKV);
        const __half2* kp = reinterpret_cast<const __half2*>(qkv + base + (size_t)tt * N_QKV + C_SZ);
        const __half2* vp = reinterpret_cast<const __half2*>(qkv + base + (size_t)tt * N_QKV + 2 * C_SZ);
        float2 f0 = __half22float2(qp[0]), f1 = __half22float2(qp[1]);
        q[tt] = make_float4(f0.x, f0.y, f1.x, f1.y);
        f0 = __half22float2(kp[0]); f1 = __half22float2(kp[1]);
        k[tt] = make_float4(f0.x, f0.y, f1.x, f1.y);
        f0 = __half22float2(vp[0]); f1 = __half22float2(vp[1]);
        v[tt] = make_float4(f0.x, f0.y, f1.x, f1.y);
    }
    float s[16];
    #pragma unroll
    for (int qt = 0; qt < 4; qt++)
        #pragma unroll
        for (int kt = 0; kt < 4; kt++)
            s[qt * 4 + kt] = q[qt].x * k[kt].x + q[qt].y * k[kt].y +
                             q[qt].z * k[kt].z + q[qt].w * k[kt].w;
    #pragma unroll
    for (int off = 16; off; off >>= 1)
        #pragma unroll
        for (int i = 0; i < 16; i++)
            s[i] += __shfl_xor_sync(0xffffffffu, s[i], off);

    #pragma unroll
    for (int qt = 0; qt < 4; qt++) {
        float sc[4];
        #pragma unroll
        for (int kt = 0; kt < 4; kt++) sc[kt] = s[qt * 4 + kt] * SCALE_F;
        float mx = fmaxf(fmaxf(sc[0], sc[1]), fmaxf(sc[2], sc[3]));
        float e[4], sum = 0.f;
        #pragma unroll
        for (int kt = 0; kt < 4; kt++) { e[kt] = __expf(sc[kt] - mx); sum += e[kt]; }
        const float inv = 1.f / sum;
        float4 acc = make_float4(0.f, 0.f, 0.f, 0.f);
        #pragma unroll
        for (int kt = 0; kt < 4; kt++) {
            const float a = e[kt] * inv;
            acc.x += a * v[kt].x; acc.y += a * v[kt].y;
            acc.z += a * v[kt].z; acc.w += a * v[kt].w;
        }
        __half2* dst = reinterpret_cast<__half2*>(
            ctx + ((size_t)b * T_SZ + qt) * C_SZ + h * DH_SZ + l * 4);
        dst[0] = __floats2half2_rn(acc.x, acc.y);
        dst[1] = __floats2half2_rn(acc.z, acc.w);
    }
}

// ---------------- LayerNorm: fp16 x -> fp32 out, per (b,t) row of C=1024 ----------------
__global__ __launch_bounds__(256) void ln_kernel(const __half* __restrict__ x,
                                                 const float* __restrict__ gamma,
                                                 const float* __restrict__ beta,
                                                 float* __restrict__ out) {
    __shared__ float rs[8], rq[8];
    const size_t row = blockIdx.x;
    const __half2* xr = reinterpret_cast<const __half2*>(x + row * C_SZ);
    const int tid = threadIdx.x;
    const float2 a0 = __half22float2(xr[tid * 2]);
    const float2 a1 = __half22float2(xr[tid * 2 + 1]);
    float4 v = make_float4(a0.x, a0.y, a1.x, a1.y);
    float s = v.x + v.y + v.z + v.w;
    float qq = v.x * v.x + v.y * v.y + v.z * v.z + v.w * v.w;
    #pragma unroll
    for (int o = 16; o; o >>= 1) {
        s  += __shfl_xor_sync(0xffffffffu, s,  o);
        qq += __shfl_xor_sync(0xffffffffu, qq, o);
    }
    if ((tid & 31) == 0) { rs[tid >> 5] = s; rq[tid >> 5] = qq; }
    __syncthreads();
    float S = 0.f, Q = 0.f;
    #pragma unroll
    for (int i = 0; i < 8; i++) { S += rs[i]; Q += rq[i]; }
    const float mu  = S * (1.f / C_SZ);
    const float var = Q * (1.f / C_SZ) - mu * mu;
    const float inv = rsqrtf(var + LN_EPS);
    const float4 g = reinterpret_cast<const float4*>(gamma)[tid];
    const float4 b = reinterpret_cast<const float4*>(beta)[tid];
    float4 o;
    o.x = (v.x - mu) * inv * g.x + b.x;
    o.y = (v.y - mu) * inv * g.y + b.y;
    o.z = (v.z - mu) * inv * g.z + b.z;
    o.w = (v.w - mu) * inv * g.w + b.w;
    reinterpret_cast<float4*>(out + row * C_SZ)[tid] = o;
}

// ---------------- launcher ----------------
extern "C" void kernel_launch(void* const* d_in, const int* in_sizes, int n_in,
                              void* d_out, int out_size) {
    (void)in_sizes; (void)n_in; (void)out_size;
    const float* feats = (const float*)d_in[0];
    const float* Wqkv  = (const float*)d_in[1];
    const float* bqkv  = (const float*)d_in[2];
    const float* Wproj = (const float*)d_in[3];
    const float* bproj = (const float*)d_in[4];
    const float* gamma = (const float*)d_in[5];
    const float* beta  = (const float*)d_in[6];
    float* out = (float*)d_out;

    __half *wqkv_h, *wproj_h, *featsh, *qkv, *ctx;
    cudaGetSymbolAddress((void**)&wqkv_h, g_Wqkv_h);
    cudaGetSymbolAddress((void**)&wproj_h, g_Wproj_h);
    cudaGetSymbolAddress((void**)&featsh, g_featsh);
    cudaGetSymbolAddress((void**)&qkv, g_qkv);
    cudaGetSymbolAddress((void**)&ctx, g_ctx);
    __half* xh = qkv;   // reuse qkv scratch for post-GEMM2 x (attn consumed qkv already)

    cudaFuncSetAttribute(gemm_kernel<N_QKV, false, true>,
                         cudaFuncAttributeMaxDynamicSharedMemorySize, GEMM_SMEM);
    cudaFuncSetAttribute(gemm_kernel<C_SZ, true, true>,
                         cudaFuncAttributeMaxDynamicSharedMemorySize, GEMM_SMEM);

    // side stream + events for prep overlap (created once; reused every call)
    static cudaStream_t s_side = nullptr;
    static cudaEvent_t  e_fork = nullptr, e_join = nullptr;
    if (s_side == nullptr) {
        cudaStreamCreateWithFlags(&s_side, cudaStreamNonBlocking);
        cudaEventCreateWithFlags(&e_fork, cudaEventDisableTiming);
        cudaEventCreateWithFlags(&e_join, cudaEventDisableTiming);
    }

    // 1. prep: weight transposes on side stream, feats convert on main stream (overlapped)
    cudaEventRecord(e_fork, 0);
    cudaStreamWaitEvent(s_side, e_fork, 0);
    transpose_kernel<<<dim3(N_QKV / 64, C_SZ / 64, T_SZ), 256, 0, s_side>>>(Wqkv, wqkv_h, C_SZ, N_QKV);
    transpose_kernel<<<dim3(C_SZ / 64, C_SZ / 64, T_SZ), 256, 0, s_side>>>(Wproj, wproj_h, C_SZ, C_SZ);
    cudaEventRecord(e_join, s_side);
    convert_kernel<<<(B_SZ * T_SZ * C_SZ / 4) / 256, 256>>>(
        (const float4*)feats, (__half2*)featsh);
    cudaStreamWaitEvent(0, e_join, 0);

    // 2. QKV projection -> fp16 qkv (fp16 mma.sync m16n8k16 + ldmatrix, 2 CTAs/SM)
    gemm_kernel<N_QKV, false, true><<<dim3(N_QKV / NT, B_SZ / MT, T_SZ), NTHR, GEMM_SMEM>>>(
        featsh, wqkv_h, bqkv, nullptr, qkv);
    // 3. cross-task attention (fp16 in, fp16 out)
    attn_kernel<<<B_SZ, 256>>>(qkv, ctx);
    // 4. output projection + bias + fp16 residual(featsh) -> fp16 x (reused qkv scratch)
    gemm_kernel<C_SZ, true, true><<<dim3(C_SZ / NT, B_SZ / MT, T_SZ), NTHR, GEMM_SMEM>>>(
        ctx, wproj_h, bproj, featsh, xh);
    // 5. LayerNorm: fp16 x -> fp32 d_out
    ln_kernel<<<B_SZ * T_SZ, 256>>>(xh, gamma, beta, out);
}